// round 11
// baseline (speedup 1.0000x reference)
#include <cuda_runtime.h>
#include <math.h>

#define S_LEN 2048
#define BATCH 64
#define INSZ  512
#define HID   512
#define BH    (BATCH * HID)          // 32768
#define GATES 1024                   // compact z|n gates
#define M_TOT (S_LEN * BATCH)        // 131072

#define NGROUP 8                     // independent batch groups
#define GSIZE  16                    // CTAs per group (j-slices)
#define BPG    8                     // batch rows per group
#define JPC    32                    // hidden units per CTA
#define WSTR   1032                  // per-j weight stride in floats (2*516)
#define HSTR   516                   // per-b h stride in floats

// 512 MB scratch for x-projection (z|n gates, bias folded in)
__device__ float g_xp[(size_t)M_TOT * GATES];
// Per-group barrier state (zero-init; reset by per-group tail handshake)
__device__ unsigned g_cnt[NGROUP];
__device__ unsigned g_sense[NGROUP];
__device__ unsigned g_done[NGROUP];

// ---------------- packed fp32x2 helpers (B300 FFMA2 pipe) ----------------
__device__ __forceinline__ void fma2(unsigned long long& d,
                                     unsigned long long a,
                                     unsigned long long b) {
    asm("fma.rn.f32x2 %0, %1, %2, %0;" : "+l"(d) : "l"(a), "l"(b));
}
__device__ __forceinline__ unsigned long long dup2(float x) {
    unsigned long long r;
    asm("mov.b64 %0, {%1, %1};" : "=l"(r) : "f"(x));
    return r;
}
__device__ __forceinline__ float2 unpack2(unsigned long long v) {
    float2 f;
    asm("mov.b64 {%0, %1}, %2;" : "=f"(f.x), "=f"(f.y) : "l"(v));
    return f;
}
// ---------------- acquire/release sync (no L1-flushing fences) -----------
__device__ __forceinline__ unsigned atom_add_acqrel(unsigned* p, unsigned v) {
    unsigned r;
    asm volatile("atom.acq_rel.gpu.add.u32 %0, [%1], %2;"
                 : "=r"(r) : "l"(p), "r"(v) : "memory");
    return r;
}
__device__ __forceinline__ unsigned ld_acq(unsigned* p) {
    unsigned r;
    asm volatile("ld.acquire.gpu.u32 %0, [%1];" : "=r"(r) : "l"(p) : "memory");
    return r;
}
__device__ __forceinline__ void st_rel(unsigned* p, unsigned v) {
    asm volatile("st.release.gpu.u32 [%0], %1;" :: "l"(p), "r"(v) : "memory");
}

// ---------------------------------------------------------------------------
// Phase 1: C[m][n] = sum_k x[m][k] * Wih[HID + n][k] + bias[HID + n]
// 128x128x8 tiled SGEMM, 256 threads, 8x8 per-thread micro-tile, FFMA2.
// ---------------------------------------------------------------------------
__global__ __launch_bounds__(256, 2) void xproj_kernel(
    const float* __restrict__ A,     // x  [M_TOT, INSZ]
    const float* __restrict__ Wih,   // [3H, INSZ]
    const float* __restrict__ bias)  // [3H]
{
    __shared__ float As[8][128];
    __shared__ float Bs[8][128];

    const int bx  = blockIdx.x;      // n tile (8)
    const int by  = blockIdx.y;      // m tile (1024)
    const int tid = threadIdx.x;

    const int lrow = tid >> 1;           // 0..127
    const int lcol = (tid & 1) * 4;      // 0 or 4

    const float* Aptr = A   + (size_t)(by * 128 + lrow) * INSZ + lcol;
    const float* Wptr = Wih + (size_t)(HID + bx * 128 + lrow) * INSZ + lcol;

    const int ty = tid >> 4;   // 0..15 (m)
    const int tx = tid & 15;   // 0..15 (n)

    unsigned long long acc[8][4];
#pragma unroll
    for (int i = 0; i < 8; i++)
#pragma unroll
        for (int j = 0; j < 4; j++) acc[i][j] = 0ULL;

    for (int k0 = 0; k0 < INSZ; k0 += 8) {
        float4 av = *(const float4*)(Aptr + k0);
        float4 bv = *(const float4*)(Wptr + k0);
        As[lcol + 0][lrow] = av.x;
        As[lcol + 1][lrow] = av.y;
        As[lcol + 2][lrow] = av.z;
        As[lcol + 3][lrow] = av.w;
        Bs[lcol + 0][lrow] = bv.x;
        Bs[lcol + 1][lrow] = bv.y;
        Bs[lcol + 2][lrow] = bv.z;
        Bs[lcol + 3][lrow] = bv.w;
        __syncthreads();

#pragma unroll
        for (int k = 0; k < 8; k++) {
            float4 a0 = *(const float4*)&As[k][ty * 8];
            float4 a1 = *(const float4*)&As[k][ty * 8 + 4];
            ulonglong2 b0 = *(const ulonglong2*)&Bs[k][tx * 8];
            ulonglong2 b1 = *(const ulonglong2*)&Bs[k][tx * 8 + 4];
            float ar[8] = {a0.x, a0.y, a0.z, a0.w, a1.x, a1.y, a1.z, a1.w};
#pragma unroll
            for (int i = 0; i < 8; i++) {
                unsigned long long ad = dup2(ar[i]);
                fma2(acc[i][0], ad, b0.x);
                fma2(acc[i][1], ad, b0.y);
                fma2(acc[i][2], ad, b1.x);
                fma2(acc[i][3], ad, b1.y);
            }
        }
        __syncthreads();
    }

    const int n0 = bx * 128 + tx * 8;
    float bv[8];
#pragma unroll
    for (int j = 0; j < 8; j++) bv[j] = bias[HID + n0 + j];

    float* Cpt = g_xp + (size_t)(by * 128 + ty * 8) * GATES + n0;
#pragma unroll
    for (int i = 0; i < 8; i++) {
        float2 p0 = unpack2(acc[i][0]);
        float2 p1 = unpack2(acc[i][1]);
        float2 p2 = unpack2(acc[i][2]);
        float2 p3 = unpack2(acc[i][3]);
        float4 o0, o1;
        o0.x = p0.x + bv[0]; o0.y = p0.y + bv[1];
        o0.z = p1.x + bv[2]; o0.w = p1.y + bv[3];
        o1.x = p2.x + bv[4]; o1.y = p2.y + bv[5];
        o1.z = p3.x + bv[6]; o1.w = p3.y + bv[7];
        *(float4*)(Cpt + (size_t)i * GATES)     = o0;
        *(float4*)(Cpt + (size_t)i * GATES + 4) = o1;
    }
}

// ---------------------------------------------------------------------------
// Phase 2: batch-grouped recurrence, register-tiled.
// 128 CTAs x 256 threads = 8 groups x 16 j-slices. Group g owns batch rows
// [8g,8g+8); CTA owns 32 hidden units (64 gate rows z|n smem-resident).
// Dot phase: thread (ks=tid>>4, bq=(tid>>3)&1, jq=tid&7) computes a 4b x 4j
// x 2-gate register tile over k-slice [ks*32, ks*32+32): 96 LDS.128 feed
// 512 fma2 (4x fewer smem bytes/FLOP than R10 — crossbar was the wall).
// Partials go to red[ks][cell][2]; thread tid then owns cell (b=tid>>5,
// j=tid&31) persistently: reduces 16 partials, applies gates, h_old in reg.
// 16-CTA per-group acq_rel barrier per step.
// ---------------------------------------------------------------------------
extern __shared__ float smem[];

__global__ __launch_bounds__(256, 1) void gru_kernel(
    const float* __restrict__ Whh,   // [3H, HID]
    float* __restrict__ out)         // [S*BH + BH]
{
    float* w_s = smem;                     // [32][1032]: z@0, n@516 per j
    float* h_s = smem + JPC * WSTR;        // [8][516]
    float* red = h_s + BPG * HSTR;         // [16][256*2] (cell*2 + gate)

    const int tid   = threadIdx.x;
    const int grp   = blockIdx.x >> 4;     // 0..7
    const int slice = blockIdx.x & 15;     // 0..15
    const int jbase = slice * JPC;

    // Dot-phase coordinates
    const int ks = tid >> 4;               // 0..15 k-slice
    const int bq = (tid >> 3) & 1;         // 0..1  b-quad
    const int jq = tid & 7;                // 0..7  j-quad
    // Persistent cell ownership (epilogue)
    const int cb = tid >> 5;               // 0..7
    const int cj = tid & 31;               // 0..31
    const int b_g = grp * BPG + cb;
    const int j_g = jbase + cj;

    // Load the 64 gate rows this CTA needs (once for the whole sequence).
    for (int i = tid; i < 64 * HID; i += 256) {
        int r = i >> 9;                    // 0..63
        int k = i & 511;
        int jl = r & 31;
        int row = ((r < 32) ? HID : 2 * HID) + jbase + jl;
        w_s[jl * WSTR + ((r < 32) ? 0 : HSTR) + k] = Whh[(size_t)row * HID + k];
    }
    __syncthreads();

    const float* hb = h_s + (bq * 4) * HSTR + ks * 32;
    const float* wb = w_s + (jq * 4) * WSTR + ks * 32;
    unsigned* cntp   = &g_cnt[grp];
    unsigned* sensep = &g_sense[grp];

    float hold = 0.f;                      // h_{t-1}(b_g, j_g)

    for (int t = 0; t < S_LEN; t++) {
        // xp prefetch for the owned cell (independent of h)
        const float* xprow = g_xp + ((size_t)t * BATCH + b_g) * GATES;
        float xpz = xprow[j_g];
        float xpn = xprow[HID + j_g];

        float sz = 0.f, sn = 0.f;
        if (t > 0) {
            // Stage this group's 8 h rows (16 KB): 4 float4 per thread.
            const float* hsrc = out + (size_t)(t - 1) * BH + (size_t)grp * BPG * HID;
#pragma unroll
            for (int r = 0; r < 4; r++) {
                int idx = tid + r * 256;
                int bb = idx >> 7, k4 = (idx & 127) << 2;
                float4 v = *(const float4*)(hsrc + bb * HID + k4);
                *(float4*)(h_s + bb * HSTR + k4) = v;
            }
            __syncthreads();

            // 4b x 4j x 2g register tile over 32 k.
            unsigned long long accz[4][4], accn[4][4];
#pragma unroll
            for (int i = 0; i < 4; i++)
#pragma unroll
                for (int j = 0; j < 4; j++) { accz[i][j] = 0ULL; accn[i][j] = 0ULL; }

#pragma unroll
            for (int kc = 0; kc < 32; kc += 4) {
                ulonglong2 h4[4], z4[4], n4[4];
#pragma unroll
                for (int i = 0; i < 4; i++)
                    h4[i] = *(const ulonglong2*)(hb + i * HSTR + kc);
#pragma unroll
                for (int j = 0; j < 4; j++) {
                    z4[j] = *(const ulonglong2*)(wb + j * WSTR + kc);
                    n4[j] = *(const ulonglong2*)(wb + j * WSTR + HSTR + kc);
                }
#pragma unroll
                for (int i = 0; i < 4; i++)
#pragma unroll
                    for (int j = 0; j < 4; j++) {
                        fma2(accz[i][j], h4[i].x, z4[j].x);
                        fma2(accz[i][j], h4[i].y, z4[j].y);
                        fma2(accn[i][j], h4[i].x, n4[j].x);
                        fma2(accn[i][j], h4[i].y, n4[j].y);
                    }
            }

            // Write partials: red[ks][cell][{z,n}], cell = b*32 + j.
            float* rp = red + ks * 512;
#pragma unroll
            for (int i = 0; i < 4; i++)
#pragma unroll
                for (int j = 0; j < 4; j++) {
                    float2 ez = unpack2(accz[i][j]);
                    float2 en = unpack2(accn[i][j]);
                    int cell = (bq * 4 + i) * 32 + jq * 4 + j;
                    float2 v = make_float2(ez.x + ez.y, en.x + en.y);
                    *(float2*)(rp + cell * 2) = v;
                }
            __syncthreads();

            // Reduce the 16 k-slice partials for the owned cell.
            const float* rq = red + tid * 2;
            float az = 0.f, bz = 0.f, an = 0.f, bn = 0.f;
#pragma unroll
            for (int s = 0; s < 16; s += 2) {
                float2 p0 = *(const float2*)(rq + s * 512);
                float2 p1 = *(const float2*)(rq + (s + 1) * 512);
                az += p0.x; an += p0.y;
                bz += p1.x; bn += p1.y;
            }
            sz = az + bz;
            sn = an + bn;
        }

        // Gates + state update (thread owns (b_g, j_g); hold in register).
        float gz = sz + xpz;
        float gn = sn + xpn;
        float z  = 1.f / (1.f + __expf(-gz));
        float e  = __expf(-2.f * fabsf(gn));        // in (0,1]
        float tt = (1.f - e) / (1.f + e);
        float n  = copysignf(tt, gn);
        float hn = (1.f - z) * n + z * hold;
        hold = hn;

        out[(size_t)t * BH + (size_t)b_g * HID + j_g] = hn;
        if (t == S_LEN - 1)
            out[(size_t)S_LEN * BH + (size_t)b_g * HID + j_g] = hn;

        __syncthreads();                   // all CTA stores issued
        if (t < S_LEN - 1) {
            // ---- per-group 16-CTA barrier (acq_rel arrivals, monotonic) ----
            if (tid == 0) {
                unsigned target = (unsigned)(t + 1) * GSIZE;
                unsigned old = atom_add_acqrel(cntp, 1u);
                if (old == target - 1u) {
                    st_rel(sensep, (unsigned)(t + 1));
                } else {
                    while (ld_acq(sensep) < (unsigned)(t + 1)) {}
                }
            }
            __syncthreads();
        }
    }

    // Per-group tail handshake: last CTA resets barrier state for next replay.
    if (tid == 0) {
        unsigned old = atom_add_acqrel(&g_done[grp], 1u);
        if (old == GSIZE - 1u) {
            st_rel(&g_cnt[grp], 0u);
            st_rel(&g_sense[grp], 0u);
            st_rel(&g_done[grp], 0u);
        }
    }
}

extern "C" void kernel_launch(void* const* d_in, const int* in_sizes, int n_in,
                              void* d_out, int out_size) {
    const float* x    = (const float*)d_in[0];
    const float* wih  = (const float*)d_in[1];
    const float* whh  = (const float*)d_in[2];
    const float* bias = (const float*)d_in[3];
    float* out = (float*)d_out;

    const size_t smem_bytes =
        (JPC * WSTR + BPG * HSTR + 16 * 512) * sizeof(float);   // ~181 KB

    static int configured = 0;
    if (!configured) {
        cudaFuncSetAttribute(gru_kernel,
                             cudaFuncAttributeMaxDynamicSharedMemorySize,
                             (int)smem_bytes);
        configured = 1;
    }

    dim3 grid1(GATES / 128, M_TOT / 128);
    xproj_kernel<<<grid1, 256>>>(x, wih, bias);

    gru_kernel<<<NGROUP * GSIZE, 256, smem_bytes>>>(whh, out);
}

// round 12
// speedup vs baseline: 1.9117x; 1.9117x over previous
#include <cuda_runtime.h>
#include <math.h>

#define S_LEN 2048
#define BATCH 64
#define INSZ  512
#define HID   512
#define BH    (BATCH * HID)          // 32768
#define GATES 1024                   // compact z|n gates
#define M_TOT (S_LEN * BATCH)        // 131072

#define NGROUP 8                     // independent batch groups
#define GSIZE  16                    // CTAs per group (j-slices)
#define BPG    8                     // batch rows per group
#define JPC    32                    // hidden units per CTA
#define HSTR   516                   // per-b h stride in floats (conflict-free)
#define GTHR   512                   // threads per gru CTA (16 warps)

// 512 MB scratch for x-projection (z|n gates, bias folded in)
__device__ float g_xp[(size_t)M_TOT * GATES];
// Per-group barrier state (zero-init; reset by per-group tail handshake)
__device__ unsigned g_cnt[NGROUP];
__device__ unsigned g_sense[NGROUP];
__device__ unsigned g_done[NGROUP];

// ---------------- packed fp32x2 helpers (B300 FFMA2 pipe) ----------------
__device__ __forceinline__ void fma2(unsigned long long& d,
                                     unsigned long long a,
                                     unsigned long long b) {
    asm("fma.rn.f32x2 %0, %1, %2, %0;" : "+l"(d) : "l"(a), "l"(b));
}
__device__ __forceinline__ unsigned long long dup2(float x) {
    unsigned long long r;
    asm("mov.b64 %0, {%1, %1};" : "=l"(r) : "f"(x));
    return r;
}
__device__ __forceinline__ float2 unpack2(unsigned long long v) {
    float2 f;
    asm("mov.b64 {%0, %1}, %2;" : "=f"(f.x), "=f"(f.y) : "l"(v));
    return f;
}
// ---------------- acquire/release sync (no L1-flushing fences) -----------
__device__ __forceinline__ unsigned atom_add_acqrel(unsigned* p, unsigned v) {
    unsigned r;
    asm volatile("atom.acq_rel.gpu.add.u32 %0, [%1], %2;"
                 : "=r"(r) : "l"(p), "r"(v) : "memory");
    return r;
}
__device__ __forceinline__ unsigned ld_acq(unsigned* p) {
    unsigned r;
    asm volatile("ld.acquire.gpu.u32 %0, [%1];" : "=r"(r) : "l"(p) : "memory");
    return r;
}
__device__ __forceinline__ void st_rel(unsigned* p, unsigned v) {
    asm volatile("st.release.gpu.u32 [%0], %1;" :: "l"(p), "r"(v) : "memory");
}

// ---------------------------------------------------------------------------
// Phase 1: C[m][n] = sum_k x[m][k] * Wih[HID + n][k] + bias[HID + n]
// 128x128x8 tiled SGEMM, 256 threads, 8x8 per-thread micro-tile, FFMA2.
// ---------------------------------------------------------------------------
__global__ __launch_bounds__(256, 2) void xproj_kernel(
    const float* __restrict__ A,     // x  [M_TOT, INSZ]
    const float* __restrict__ Wih,   // [3H, INSZ]
    const float* __restrict__ bias)  // [3H]
{
    __shared__ float As[8][128];
    __shared__ float Bs[8][128];

    const int bx  = blockIdx.x;      // n tile (8)
    const int by  = blockIdx.y;      // m tile (1024)
    const int tid = threadIdx.x;

    const int lrow = tid >> 1;           // 0..127
    const int lcol = (tid & 1) * 4;      // 0 or 4

    const float* Aptr = A   + (size_t)(by * 128 + lrow) * INSZ + lcol;
    const float* Wptr = Wih + (size_t)(HID + bx * 128 + lrow) * INSZ + lcol;

    const int ty = tid >> 4;   // 0..15 (m)
    const int tx = tid & 15;   // 0..15 (n)

    unsigned long long acc[8][4];
#pragma unroll
    for (int i = 0; i < 8; i++)
#pragma unroll
        for (int j = 0; j < 4; j++) acc[i][j] = 0ULL;

    for (int k0 = 0; k0 < INSZ; k0 += 8) {
        float4 av = *(const float4*)(Aptr + k0);
        float4 bv = *(const float4*)(Wptr + k0);
        As[lcol + 0][lrow] = av.x;
        As[lcol + 1][lrow] = av.y;
        As[lcol + 2][lrow] = av.z;
        As[lcol + 3][lrow] = av.w;
        Bs[lcol + 0][lrow] = bv.x;
        Bs[lcol + 1][lrow] = bv.y;
        Bs[lcol + 2][lrow] = bv.z;
        Bs[lcol + 3][lrow] = bv.w;
        __syncthreads();

#pragma unroll
        for (int k = 0; k < 8; k++) {
            float4 a0 = *(const float4*)&As[k][ty * 8];
            float4 a1 = *(const float4*)&As[k][ty * 8 + 4];
            ulonglong2 b0 = *(const ulonglong2*)&Bs[k][tx * 8];
            ulonglong2 b1 = *(const ulonglong2*)&Bs[k][tx * 8 + 4];
            float ar[8] = {a0.x, a0.y, a0.z, a0.w, a1.x, a1.y, a1.z, a1.w};
#pragma unroll
            for (int i = 0; i < 8; i++) {
                unsigned long long ad = dup2(ar[i]);
                fma2(acc[i][0], ad, b0.x);
                fma2(acc[i][1], ad, b0.y);
                fma2(acc[i][2], ad, b1.x);
                fma2(acc[i][3], ad, b1.y);
            }
        }
        __syncthreads();
    }

    const int n0 = bx * 128 + tx * 8;
    float bv[8];
#pragma unroll
    for (int j = 0; j < 8; j++) bv[j] = bias[HID + n0 + j];

    float* Cpt = g_xp + (size_t)(by * 128 + ty * 8) * GATES + n0;
#pragma unroll
    for (int i = 0; i < 8; i++) {
        float2 p0 = unpack2(acc[i][0]);
        float2 p1 = unpack2(acc[i][1]);
        float2 p2 = unpack2(acc[i][2]);
        float2 p3 = unpack2(acc[i][3]);
        float4 o0, o1;
        o0.x = p0.x + bv[0]; o0.y = p0.y + bv[1];
        o0.z = p1.x + bv[2]; o0.w = p1.y + bv[3];
        o1.x = p2.x + bv[4]; o1.y = p2.y + bv[5];
        o1.z = p3.x + bv[6]; o1.w = p3.y + bv[7];
        *(float4*)(Cpt + (size_t)i * GATES)     = o0;
        *(float4*)(Cpt + (size_t)i * GATES + 4) = o1;
    }
}

// ---------------------------------------------------------------------------
// Phase 2: batch-grouped recurrence, WEIGHTS IN REGISTERS.
// 128 CTAs x 512 threads = 8 groups x 16 j-slices. Group g owns batch rows
// [8g,8g+8); CTA owns 32 hidden units. Thread (lane=j_l, warp=(gate, ks)):
// holds its 64-float weight slice (gate row j, k in [ks*64, ks*64+64)) in 32
// packed registers, loaded ONCE. Per step: h staged to smem (16 KB), dot via
// broadcast LDS (one address/warp) against register weights, scalar partial
// per b to part[warp][b][j] (conflict-free), then 256 owner threads reduce
// 16 partials, apply gates (h_old in register), store h.
// 16-CTA per-group acq_rel barrier per step.
// ---------------------------------------------------------------------------
__global__ __launch_bounds__(GTHR) void gru_kernel(
    const float* __restrict__ Whh,   // [3H, HID]
    float* __restrict__ out)         // [S*BH + BH]
{
    __shared__ float h_s[BPG * HSTR];        // 8 x 516
    __shared__ float part[16 * BPG * JPC];   // [warp][b][j]

    const int tid   = threadIdx.x;
    const int lane  = tid & 31;          // j within CTA
    const int warp  = tid >> 5;          // 0..15
    const int g     = warp & 1;          // 0 = z, 1 = n
    const int ks    = warp >> 1;         // 0..7 k-slice (64 k each)
    const int grp   = blockIdx.x >> 4;   // 0..7
    const int slice = blockIdx.x & 15;   // 0..15
    const int jbase = slice * JPC;
    // Owner cell (epilogue): threads 0..255 own (ob, oj)
    const int ob  = tid >> 5;            // 0..7 (valid when tid < 256)
    const int oj  = tid & 31;
    const int b_g = grp * BPG + ob;
    const int j_g = jbase + oj;

    // ---- Load this thread's weight slice into registers (once) ----
    unsigned long long wr[32];
    {
        int row = (g ? 2 * HID : HID) + jbase + lane;
        const float* wrow = Whh + (size_t)row * HID + ks * 64;
#pragma unroll
        for (int i = 0; i < 16; i++) {
            ulonglong2 v = *(const ulonglong2*)(wrow + i * 4);
            wr[2 * i]     = v.x;
            wr[2 * i + 1] = v.y;
        }
    }

    unsigned* cntp   = &g_cnt[grp];
    unsigned* sensep = &g_sense[grp];

    float hold = 0.f;                    // h_{t-1}(b_g, j_g), owners only

    for (int t = 0; t < S_LEN; t++) {
        // xp prefetch for the owned cell (independent of h)
        float xpz = 0.f, xpn = 0.f;
        if (tid < 256) {
            const float* xprow = g_xp + ((size_t)t * BATCH + b_g) * GATES;
            xpz = xprow[j_g];
            xpn = xprow[HID + j_g];
        }

        float sz = 0.f, sn = 0.f;
        if (t > 0) {
            // Stage this group's 8 h rows (16 KB): two float4 per thread.
            const float* hsrc = out + (size_t)(t - 1) * BH + (size_t)grp * BPG * HID;
#pragma unroll
            for (int r = 0; r < 2; r++) {
                int idx = tid + r * GTHR;
                int bb = idx >> 7, k4 = (idx & 127) << 2;
                *(float4*)(h_s + bb * HSTR + k4) = *(const float4*)(hsrc + bb * HID + k4);
            }
            __syncthreads();

            // Dot: for each b, 64-k packed dot against register weights.
            // h loads are warp-uniform addresses -> pure broadcast.
            const float* hbase = h_s + ks * 64;
#pragma unroll 2
            for (int b = 0; b < 8; b++) {
                const float* hp = hbase + b * HSTR;
                unsigned long long a0 = 0ULL, a1 = 0ULL;
#pragma unroll
                for (int c = 0; c < 4; c++) {
                    ulonglong2 hA = *(const ulonglong2*)(hp + c * 16);
                    ulonglong2 hB = *(const ulonglong2*)(hp + c * 16 + 4);
                    ulonglong2 hC = *(const ulonglong2*)(hp + c * 16 + 8);
                    ulonglong2 hD = *(const ulonglong2*)(hp + c * 16 + 12);
                    fma2(a0, hA.x, wr[c * 8 + 0]); fma2(a1, hA.y, wr[c * 8 + 1]);
                    fma2(a0, hB.x, wr[c * 8 + 2]); fma2(a1, hB.y, wr[c * 8 + 3]);
                    fma2(a0, hC.x, wr[c * 8 + 4]); fma2(a1, hC.y, wr[c * 8 + 5]);
                    fma2(a0, hD.x, wr[c * 8 + 6]); fma2(a1, hD.y, wr[c * 8 + 7]);
                }
                float2 u = unpack2(a0), v = unpack2(a1);
                part[warp * (BPG * JPC) + b * JPC + lane] = (u.x + u.y) + (v.x + v.y);
            }
            __syncthreads();

            // Owners reduce the 8 k-slice partials per gate.
            if (tid < 256) {
                const float* pp = part + ob * JPC + oj;
                float sz0 = 0.f, sz1 = 0.f, sn0 = 0.f, sn1 = 0.f;
#pragma unroll
                for (int s = 0; s < 8; s += 2) {
                    sz0 += pp[(2 * s    ) * (BPG * JPC)];   // warp 2s   (g=0)
                    sn0 += pp[(2 * s + 1) * (BPG * JPC)];   // warp 2s+1 (g=1)
                    sz1 += pp[(2 * s + 2) * (BPG * JPC)];
                    sn1 += pp[(2 * s + 3) * (BPG * JPC)];
                }
                sz = sz0 + sz1;
                sn = sn0 + sn1;
            }
        }

        if (tid < 256) {
            // Gates + state update (thread owns (b_g, j_g); hold in register).
            float gz = sz + xpz;
            float gn = sn + xpn;
            float z  = 1.f / (1.f + __expf(-gz));
            float e  = __expf(-2.f * fabsf(gn));        // in (0,1]
            float tt = (1.f - e) / (1.f + e);
            float n  = copysignf(tt, gn);
            float hn = (1.f - z) * n + z * hold;
            hold = hn;

            out[(size_t)t * BH + (size_t)b_g * HID + j_g] = hn;
            if (t == S_LEN - 1)
                out[(size_t)S_LEN * BH + (size_t)b_g * HID + j_g] = hn;
        }

        __syncthreads();                   // all CTA stores issued
        if (t < S_LEN - 1) {
            // ---- per-group 16-CTA barrier (acq_rel arrivals, monotonic) ----
            if (tid == 0) {
                unsigned target = (unsigned)(t + 1) * GSIZE;
                unsigned old = atom_add_acqrel(cntp, 1u);
                if (old == target - 1u) {
                    st_rel(sensep, (unsigned)(t + 1));
                } else {
                    while (ld_acq(sensep) < (unsigned)(t + 1)) {}
                }
            }
            __syncthreads();
        }
    }

    // Per-group tail handshake: last CTA resets barrier state for next replay.
    if (tid == 0) {
        unsigned old = atom_add_acqrel(&g_done[grp], 1u);
        if (old == GSIZE - 1u) {
            st_rel(&g_cnt[grp], 0u);
            st_rel(&g_sense[grp], 0u);
            st_rel(&g_done[grp], 0u);
        }
    }
}

extern "C" void kernel_launch(void* const* d_in, const int* in_sizes, int n_in,
                              void* d_out, int out_size) {
    const float* x    = (const float*)d_in[0];
    const float* wih  = (const float*)d_in[1];
    const float* whh  = (const float*)d_in[2];
    const float* bias = (const float*)d_in[3];
    float* out = (float*)d_out;

    dim3 grid1(GATES / 128, M_TOT / 128);
    xproj_kernel<<<grid1, 256>>>(x, wih, bias);

    gru_kernel<<<NGROUP * GSIZE, GTHR>>>(whh, out);
}

// round 13
// speedup vs baseline: 2.1669x; 1.1335x over previous
#include <cuda_runtime.h>
#include <math.h>

#define S_LEN 2048
#define BATCH 64
#define INSZ  512
#define HID   512
#define BH    (BATCH * HID)          // 32768
#define GATES 1024                   // compact z|n gates
#define M_TOT (S_LEN * BATCH)        // 131072

#define NGROUP 8                     // independent batch groups
#define GSIZE  16                    // CTAs per group (j-slices)
#define BPG    8                     // batch rows per group
#define JPC    32                    // hidden units per CTA
#define HSTR   516                   // per-b h stride in floats (conflict-free)
#define GTHR   512                   // threads per gru CTA (16 warps)

// 512 MB scratch for x-projection (z|n gates, bias folded in)
__device__ float g_xp[(size_t)M_TOT * GATES];
// Per-group barrier state (zero-init; reset by per-group tail handshake)
__device__ unsigned g_cnt[NGROUP];
__device__ unsigned g_sense[NGROUP];
__device__ unsigned g_done[NGROUP];

// ---------------- packed fp32x2 helpers (B300 FFMA2 pipe) ----------------
__device__ __forceinline__ void fma2(unsigned long long& d,
                                     unsigned long long a,
                                     unsigned long long b) {
    asm("fma.rn.f32x2 %0, %1, %2, %0;" : "+l"(d) : "l"(a), "l"(b));
}
__device__ __forceinline__ unsigned long long dup2(float x) {
    unsigned long long r;
    asm("mov.b64 %0, {%1, %1};" : "=l"(r) : "f"(x));
    return r;
}
__device__ __forceinline__ float2 unpack2(unsigned long long v) {
    float2 f;
    asm("mov.b64 {%0, %1}, %2;" : "=f"(f.x), "=f"(f.y) : "l"(v));
    return f;
}
// ---------------- acquire/release sync (no L1-flushing fences) -----------
__device__ __forceinline__ unsigned atom_add_acqrel(unsigned* p, unsigned v) {
    unsigned r;
    asm volatile("atom.acq_rel.gpu.add.u32 %0, [%1], %2;"
                 : "=r"(r) : "l"(p), "r"(v) : "memory");
    return r;
}
__device__ __forceinline__ unsigned ld_acq(unsigned* p) {
    unsigned r;
    asm volatile("ld.acquire.gpu.u32 %0, [%1];" : "=r"(r) : "l"(p) : "memory");
    return r;
}
__device__ __forceinline__ void st_rel(unsigned* p, unsigned v) {
    asm volatile("st.release.gpu.u32 [%0], %1;" :: "l"(p), "r"(v) : "memory");
}

// ---------------------------------------------------------------------------
// Phase 1: C[m][n] = sum_k x[m][k] * Wih[HID + n][k] + bias[HID + n]
// 128x128x8 tiled SGEMM, ping-pong smem (ONE sync/iter), LDG prefetch hidden
// under the FFMA2 block. 256 threads, 8x8 micro-tile.
// ---------------------------------------------------------------------------
__global__ __launch_bounds__(256, 2) void xproj_kernel(
    const float* __restrict__ A,     // x  [M_TOT, INSZ]
    const float* __restrict__ Wih,   // [3H, INSZ]
    const float* __restrict__ bias)  // [3H]
{
    __shared__ float As[2][8][128];
    __shared__ float Bs[2][8][128];

    const int bx  = blockIdx.x;      // n tile (8)
    const int by  = blockIdx.y;      // m tile (1024)
    const int tid = threadIdx.x;

    const int lrow = tid >> 1;           // 0..127
    const int lcol = (tid & 1) * 4;      // 0 or 4

    const float* Aptr = A   + (size_t)(by * 128 + lrow) * INSZ + lcol;
    const float* Wptr = Wih + (size_t)(HID + bx * 128 + lrow) * INSZ + lcol;

    const int ty = tid >> 4;   // 0..15 (m)
    const int tx = tid & 15;   // 0..15 (n)

    unsigned long long acc[8][4];
#pragma unroll
    for (int i = 0; i < 8; i++)
#pragma unroll
        for (int j = 0; j < 4; j++) acc[i][j] = 0ULL;

    // Preload tile 0 into buffer 0.
    {
        float4 av = *(const float4*)(Aptr);
        float4 bv = *(const float4*)(Wptr);
        As[0][lcol + 0][lrow] = av.x; As[0][lcol + 1][lrow] = av.y;
        As[0][lcol + 2][lrow] = av.z; As[0][lcol + 3][lrow] = av.w;
        Bs[0][lcol + 0][lrow] = bv.x; Bs[0][lcol + 1][lrow] = bv.y;
        Bs[0][lcol + 2][lrow] = bv.z; Bs[0][lcol + 3][lrow] = bv.w;
    }
    __syncthreads();

    for (int k0 = 0; k0 < INSZ; k0 += 8) {
        const int p = (k0 >> 3) & 1;
        float4 av, bv;
        const bool more = (k0 + 8 < INSZ);
        if (more) {                      // issue LDG early; consume after FMAs
            av = *(const float4*)(Aptr + k0 + 8);
            bv = *(const float4*)(Wptr + k0 + 8);
        }

#pragma unroll
        for (int k = 0; k < 8; k++) {
            float4 a0 = *(const float4*)&As[p][k][ty * 8];
            float4 a1 = *(const float4*)&As[p][k][ty * 8 + 4];
            ulonglong2 b0 = *(const ulonglong2*)&Bs[p][k][tx * 8];
            ulonglong2 b1 = *(const ulonglong2*)&Bs[p][k][tx * 8 + 4];
            float ar[8] = {a0.x, a0.y, a0.z, a0.w, a1.x, a1.y, a1.z, a1.w};
#pragma unroll
            for (int i = 0; i < 8; i++) {
                unsigned long long ad = dup2(ar[i]);
                fma2(acc[i][0], ad, b0.x);
                fma2(acc[i][1], ad, b0.y);
                fma2(acc[i][2], ad, b1.x);
                fma2(acc[i][3], ad, b1.y);
            }
        }

        if (more) {
            const int q = 1 - p;
            As[q][lcol + 0][lrow] = av.x; As[q][lcol + 1][lrow] = av.y;
            As[q][lcol + 2][lrow] = av.z; As[q][lcol + 3][lrow] = av.w;
            Bs[q][lcol + 0][lrow] = bv.x; Bs[q][lcol + 1][lrow] = bv.y;
            Bs[q][lcol + 2][lrow] = bv.z; Bs[q][lcol + 3][lrow] = bv.w;
        }
        __syncthreads();
    }

    const int n0 = bx * 128 + tx * 8;
    float bvs[8];
#pragma unroll
    for (int j = 0; j < 8; j++) bvs[j] = bias[HID + n0 + j];

    float* Cpt = g_xp + (size_t)(by * 128 + ty * 8) * GATES + n0;
#pragma unroll
    for (int i = 0; i < 8; i++) {
        float2 p0 = unpack2(acc[i][0]);
        float2 p1 = unpack2(acc[i][1]);
        float2 p2 = unpack2(acc[i][2]);
        float2 p3 = unpack2(acc[i][3]);
        float4 o0, o1;
        o0.x = p0.x + bvs[0]; o0.y = p0.y + bvs[1];
        o0.z = p1.x + bvs[2]; o0.w = p1.y + bvs[3];
        o1.x = p2.x + bvs[4]; o1.y = p2.y + bvs[5];
        o1.z = p3.x + bvs[6]; o1.w = p3.y + bvs[7];
        *(float4*)(Cpt + (size_t)i * GATES)     = o0;
        *(float4*)(Cpt + (size_t)i * GATES + 4) = o1;
    }
}

// ---------------------------------------------------------------------------
// Phase 2: batch-grouped recurrence, BOTH gate rows in registers.
// 128 CTAs x 512 threads = 8 groups x 16 j-slices. Thread (lane=j, warp=ks):
// holds z AND n weight slices (k in [ks*32, ks*32+32)) in 32 packed regs.
// Per step per b: 8 broadcast LDS.128 of h feed 32 fma2 (1:4 ratio — R12's
// z/n warp split loaded every h value twice). Partials as float2 (z,n) in
// part[warp][b][j]; owner threads (tid<256) reduce 16 slices, apply gates
// (h_old in register). 16-CTA per-group acq_rel barrier per step.
// ---------------------------------------------------------------------------
__global__ __launch_bounds__(GTHR) void gru_kernel(
    const float* __restrict__ Whh,   // [3H, HID]
    float* __restrict__ out)         // [S*BH + BH]
{
    __shared__ float h_s[BPG * HSTR];            // 8 x 516
    __shared__ float part[16 * BPG * JPC * 2];   // [warp][b][j][{z,n}] 32 KB

    const int tid   = threadIdx.x;
    const int lane  = tid & 31;          // j within CTA
    const int warp  = tid >> 5;          // 0..15 = k-slice (32 k each)
    const int grp   = blockIdx.x >> 4;   // 0..7
    const int slice = blockIdx.x & 15;   // 0..15
    const int jbase = slice * JPC;
    // Owner cell (epilogue): threads 0..255 own (ob, oj)
    const int ob  = tid >> 5;            // 0..7 (valid when tid < 256)
    const int oj  = tid & 31;
    const int b_g = grp * BPG + ob;
    const int j_g = jbase + oj;

    // ---- Load this thread's z and n weight slices into registers (once) ----
    unsigned long long wz[16], wn[16];
    {
        const float* zrow = Whh + (size_t)(HID     + jbase + lane) * HID + warp * 32;
        const float* nrow = Whh + (size_t)(2 * HID + jbase + lane) * HID + warp * 32;
#pragma unroll
        for (int i = 0; i < 8; i++) {
            ulonglong2 vz = *(const ulonglong2*)(zrow + i * 4);
            wz[2 * i]     = vz.x;
            wz[2 * i + 1] = vz.y;
        }
#pragma unroll
        for (int i = 0; i < 8; i++) {
            ulonglong2 vn = *(const ulonglong2*)(nrow + i * 4);
            wn[2 * i]     = vn.x;
            wn[2 * i + 1] = vn.y;
        }
    }

    unsigned* cntp   = &g_cnt[grp];
    unsigned* sensep = &g_sense[grp];

    float hold = 0.f;                    // h_{t-1}(b_g, j_g), owners only

    for (int t = 0; t < S_LEN; t++) {
        // xp prefetch for the owned cell (independent of h)
        float xpz = 0.f, xpn = 0.f;
        if (tid < 256) {
            const float* xprow = g_xp + ((size_t)t * BATCH + b_g) * GATES;
            xpz = xprow[j_g];
            xpn = xprow[HID + j_g];
        }

        float sz = 0.f, sn = 0.f;
        if (t > 0) {
            // Stage this group's 8 h rows (16 KB): two float4 per thread.
            const float* hsrc = out + (size_t)(t - 1) * BH + (size_t)grp * BPG * HID;
#pragma unroll
            for (int r = 0; r < 2; r++) {
                int idx = tid + r * GTHR;
                int bb = idx >> 7, k4 = (idx & 127) << 2;
                *(float4*)(h_s + bb * HSTR + k4) = *(const float4*)(hsrc + bb * HID + k4);
            }
            __syncthreads();

            // Dot: for each b, 32-k packed dot (both gates) vs register weights.
            const float* hbase = h_s + warp * 32;
#pragma unroll 2
            for (int b = 0; b < 8; b++) {
                const float* hp = hbase + b * HSTR;
                unsigned long long az0 = 0ULL, az1 = 0ULL;
                unsigned long long an0 = 0ULL, an1 = 0ULL;
#pragma unroll
                for (int c = 0; c < 8; c++) {
                    ulonglong2 h2 = *(const ulonglong2*)(hp + c * 4);
                    fma2(az0, h2.x, wz[2 * c]);
                    fma2(az1, h2.y, wz[2 * c + 1]);
                    fma2(an0, h2.x, wn[2 * c]);
                    fma2(an1, h2.y, wn[2 * c + 1]);
                }
                float2 ez0 = unpack2(az0), ez1 = unpack2(az1);
                float2 en0 = unpack2(an0), en1 = unpack2(an1);
                float2 v = make_float2((ez0.x + ez0.y) + (ez1.x + ez1.y),
                                       (en0.x + en0.y) + (en1.x + en1.y));
                *(float2*)(part + (warp * 256 + b * 32 + lane) * 2) = v;
            }
            __syncthreads();

            // Owners reduce the 16 k-slice partials (float2 = both gates).
            if (tid < 256) {
                const float* pp = part + (ob * 32 + oj) * 2;
                float sza = 0.f, szb = 0.f, sna = 0.f, snb = 0.f;
#pragma unroll
                for (int s = 0; s < 16; s += 2) {
                    float2 p0 = *(const float2*)(pp + s * 512);
                    float2 p1 = *(const float2*)(pp + (s + 1) * 512);
                    sza += p0.x; sna += p0.y;
                    szb += p1.x; snb += p1.y;
                }
                sz = sza + szb;
                sn = sna + snb;
            }
        }

        if (tid < 256) {
            // Gates + state update (thread owns (b_g, j_g); hold in register).
            float gz = sz + xpz;
            float gn = sn + xpn;
            float z  = 1.f / (1.f + __expf(-gz));
            float e  = __expf(-2.f * fabsf(gn));        // in (0,1]
            float tt = (1.f - e) / (1.f + e);
            float n  = copysignf(tt, gn);
            float hn = (1.f - z) * n + z * hold;
            hold = hn;

            out[(size_t)t * BH + (size_t)b_g * HID + j_g] = hn;
            if (t == S_LEN - 1)
                out[(size_t)S_LEN * BH + (size_t)b_g * HID + j_g] = hn;
        }

        __syncthreads();                   // all CTA stores issued
        if (t < S_LEN - 1) {
            // ---- per-group 16-CTA barrier (acq_rel arrivals, monotonic) ----
            if (tid == 0) {
                unsigned target = (unsigned)(t + 1) * GSIZE;
                unsigned old = atom_add_acqrel(cntp, 1u);
                if (old == target - 1u) {
                    st_rel(sensep, (unsigned)(t + 1));
                } else {
                    while (ld_acq(sensep) < (unsigned)(t + 1)) {}
                }
            }
            __syncthreads();
        }
    }

    // Per-group tail handshake: last CTA resets barrier state for next replay.
    if (tid == 0) {
        unsigned old = atom_add_acqrel(&g_done[grp], 1u);
        if (old == GSIZE - 1u) {
            st_rel(&g_cnt[grp], 0u);
            st_rel(&g_sense[grp], 0u);
            st_rel(&g_done[grp], 0u);
        }
    }
}

extern "C" void kernel_launch(void* const* d_in, const int* in_sizes, int n_in,
                              void* d_out, int out_size) {
    const float* x    = (const float*)d_in[0];
    const float* wih  = (const float*)d_in[1];
    const float* whh  = (const float*)d_in[2];
    const float* bias = (const float*)d_in[3];
    float* out = (float*)d_out;

    dim3 grid1(GATES / 128, M_TOT / 128);
    xproj_kernel<<<grid1, 256>>>(x, wih, bias);

    gru_kernel<<<NGROUP * GSIZE, GTHR>>>(whh, out);
}